// round 4
// baseline (speedup 1.0000x reference)
#include <cuda_runtime.h>
#include <cuda_fp16.h>
#include <cstdint>

// ============================================================================
// PhaseCoherenceComputer: C[bh,q,k] = mean_h cos(phq - phk)
//   = (cos_q @ cos_k^T + sin_q @ sin_k^T) / 64
// 16 GEMMs [2048,128]@[128,2048]^T in fp16 (validated rel_err ~5.6e-5).
// 1/64 folded into A scratch. Scratch row (K=128 fp16): cos[0:64] sin[64:128].
// R4: single K-stage (BK=128), smem-staged coalesced st.global.cs epilogue.
// ============================================================================

#define NBH 16
#define SEQ 2048
#define NH  64
#define KS  128
#define BM  128
#define BN  128
#define BK  128

// ---------------- scratch (device globals; no allocation APIs) --------------
__device__ __align__(16) __half gA[NBH * SEQ * KS];   // 8 MB (pre-scaled 1/64)
__device__ __align__(16) __half gB[NBH * SEQ * KS];   // 8 MB

__device__ __forceinline__ uint32_t smem_u32(const void* p) {
    uint32_t a;
    asm("{ .reg .u64 t; cvta.to.shared.u64 t, %1; cvt.u32.u64 %0, t; }"
        : "=r"(a) : "l"(p));
    return a;
}

#define CP_ASYNC_16(smem, gptr)                                                \
    asm volatile("cp.async.cg.shared.global [%0], [%1], 16;"                   \
                 :: "r"(smem), "l"(gptr))
#define CP_COMMIT()  asm volatile("cp.async.commit_group;" ::: "memory")
#define CP_WAIT(N)   asm volatile("cp.async.wait_group %0;" :: "n"(N) : "memory")

#define LDSM_X4(r0, r1, r2, r3, addr)                                          \
    asm volatile("ldmatrix.sync.aligned.m8n8.x4.shared.b16 {%0,%1,%2,%3}, [%4];" \
                 : "=r"(r0), "=r"(r1), "=r"(r2), "=r"(r3) : "r"(addr))

#define MMA_F16(c0, c1, c2, c3, a0, a1, a2, a3, b0, b1)                        \
    asm volatile("mma.sync.aligned.m16n8k16.row.col.f32.f16.f16.f32 "          \
                 "{%0,%1,%2,%3}, {%4,%5,%6,%7}, {%8,%9}, {%0,%1,%2,%3};"       \
                 : "+f"(c0), "+f"(c1), "+f"(c2), "+f"(c3)                      \
                 : "r"(a0), "r"(a1), "r"(a2), "r"(a3), "r"(b0), "r"(b1))

#define STG_CS_V4(gptr, x, y, z, w)                                            \
    asm volatile("st.global.cs.v4.f32 [%0], {%1,%2,%3,%4};"                    \
                 :: "l"(gptr), "f"(x), "f"(y), "f"(z), "f"(w) : "memory")

// ============================================================================
// Kernel 1: sincos -> fp16 scratch (A pre-scaled 1/NH). 4 harmonics/thread.
// ============================================================================
__global__ void phase_prep_kernel(const float* __restrict__ q,
                                  const float* __restrict__ k)
{
    const int NT = NBH * SEQ * (NH / 4);
    int idx = blockIdx.x * blockDim.x + threadIdx.x;
    if (idx >= 2 * NT) return;
    bool isQ = idx < NT;
    int li  = isQ ? idx : idx - NT;
    int row = li >> 4;
    int h4  = (li & 15) << 2;

    const float4 v = *(const float4*)((isQ ? q : k) + (size_t)row * NH + h4);
    const float sc = isQ ? (1.0f / (float)NH) : 1.0f;

    float s0, c0, s1, c1, s2, c2, s3, c3;
    sincosf(v.x, &s0, &c0);
    sincosf(v.y, &s1, &c1);
    sincosf(v.z, &s2, &c2);
    sincosf(v.w, &s3, &c3);

    __half2 ca = __floats2half2_rn(c0 * sc, c1 * sc);
    __half2 cb = __floats2half2_rn(c2 * sc, c3 * sc);
    __half2 sa = __floats2half2_rn(s0 * sc, s1 * sc);
    __half2 sb = __floats2half2_rn(s2 * sc, s3 * sc);

    __half* dst = (isQ ? gA : gB) + (size_t)row * KS;
    uint2 uc, us;
    uc.x = *reinterpret_cast<uint32_t*>(&ca);
    uc.y = *reinterpret_cast<uint32_t*>(&cb);
    us.x = *reinterpret_cast<uint32_t*>(&sa);
    us.y = *reinterpret_cast<uint32_t*>(&sb);
    *(uint2*)(dst + h4)      = uc;
    *(uint2*)(dst + 64 + h4) = us;
}

// ============================================================================
// Kernel 2: fp16 mma.sync GEMM, BM=BN=128, single BK=128 stage.
// grid (16,16,16), 256 threads = 2x4 warps of 64x32.
// smem: phase A = A tile 32KB + B tile 32KB (256B rows, XOR swizzle)
//       phase B = 128x136 fp32 epilogue tile (reused), 69632 B total.
// ============================================================================
#define A_BYTES   (BM * BK * 2)               // 32768
#define EPI_STRIDE 136                         // floats; 8-bank shift per row
#define SMEM_TOTAL (BM * EPI_STRIDE * 4)       // 69632 > 65536 tile bytes

__global__ void __launch_bounds__(256, 2)
phase_gemm_kernel(float* __restrict__ out)
{
    extern __shared__ char smem[];
    const uint32_t sb = smem_u32(smem);
    const int tid  = threadIdx.x;
    const int wid  = tid >> 5;
    const int lane = tid & 31;
    const int wm   = wid >> 2;          // 0-1
    const int wn   = wid & 3;           // 0-3

    const int nt = blockIdx.x;
    const int mt = blockIdx.y;
    const int bh = blockIdx.z;

    const __half* __restrict__ pA = gA + ((size_t)bh * SEQ + (size_t)mt * BM) * KS;
    const __half* __restrict__ pB = gB + ((size_t)bh * SEQ + (size_t)nt * BN) * KS;

    // ---- load A,B tiles: 128 rows x 256B, 16 chunks/row, XOR-swizzled ----
    // thread -> (row = tid>>4 (+16 per t), chunk = tid&15); 8 iters per tile
    {
        const int r0 = tid >> 4;
        const int c  = tid & 15;
#pragma unroll
        for (int t = 0; t < 8; t++) {
            int row = r0 + t * 16;
            uint32_t sw = (uint32_t)((c & 8) | ((c & 7) ^ (row & 7)));
            uint32_t so = (uint32_t)(row * 256) + (sw << 4);
            size_t   go = (size_t)row * KS + c * 8;
            CP_ASYNC_16(sb + so,           pA + go);
            CP_ASYNC_16(sb + A_BYTES + so, pB + go);
        }
        CP_COMMIT();
    }

    // ldmatrix base rows
    const int rl = lane & 15;
    const int hc = lane >> 4;
    uint32_t aRow[4], bRow[2];
#pragma unroll
    for (int mf = 0; mf < 4; mf++) aRow[mf] = (uint32_t)(wm * 64 + mf * 16 + rl);
#pragma unroll
    for (int p = 0; p < 2; p++)   bRow[p]  = (uint32_t)(wn * 32 + p * 16 + rl);

    float acc[4][4][4];
#pragma unroll
    for (int mf = 0; mf < 4; mf++)
#pragma unroll
        for (int nf = 0; nf < 4; nf++)
#pragma unroll
            for (int j = 0; j < 4; j++) acc[mf][nf][j] = 0.0f;

    CP_WAIT(0);
    __syncthreads();

    // ---- mainloop: 8 k-slices of 16 ----
#pragma unroll
    for (int kk = 0; kk < 8; kk++) {
        const uint32_t chunk = (uint32_t)(kk * 2 + hc);   // 0-15
        uint32_t a[4][4];
#pragma unroll
        for (int mf = 0; mf < 4; mf++) {
            uint32_t r = aRow[mf];
            uint32_t sw = (chunk & 8) | ((chunk & 7) ^ (r & 7));
            LDSM_X4(a[mf][0], a[mf][1], a[mf][2], a[mf][3],
                    sb + r * 256 + (sw << 4));
        }
        uint32_t b[4][2];
#pragma unroll
        for (int p = 0; p < 2; p++) {
            uint32_t r = bRow[p];
            uint32_t sw = (chunk & 8) | ((chunk & 7) ^ (r & 7));
            uint32_t r0, r1, r2, r3;
            LDSM_X4(r0, r1, r2, r3, sb + A_BYTES + r * 256 + (sw << 4));
            b[p * 2][0]     = r0; b[p * 2][1]     = r2;
            b[p * 2 + 1][0] = r1; b[p * 2 + 1][1] = r3;
        }
#pragma unroll
        for (int mf = 0; mf < 4; mf++)
#pragma unroll
            for (int nf = 0; nf < 4; nf++)
                MMA_F16(acc[mf][nf][0], acc[mf][nf][1],
                        acc[mf][nf][2], acc[mf][nf][3],
                        a[mf][0], a[mf][1], a[mf][2], a[mf][3],
                        b[nf][0], b[nf][1]);
    }

    // ---- epilogue: stage fp32 tile in smem, stream out coalesced ----
    __syncthreads();   // tiles no longer needed; smem being repurposed

    {
        const int qg  = lane >> 2;
        const int cp2 = (lane & 3) * 2;
        float* ep = (float*)smem;
#pragma unroll
        for (int mf = 0; mf < 4; mf++) {
            const int row0 = wm * 64 + mf * 16 + qg;
#pragma unroll
            for (int nf = 0; nf < 4; nf++) {
                const int col = wn * 32 + nf * 8 + cp2;
                float* p0 = ep + (size_t)row0 * EPI_STRIDE + col;
                *(float2*)p0 = make_float2(acc[mf][nf][0], acc[mf][nf][1]);
                *(float2*)(p0 + 8 * EPI_STRIDE) =
                    make_float2(acc[mf][nf][2], acc[mf][nf][3]);
            }
        }
    }
    __syncthreads();

    {
        const float* ep = (const float*)smem;
        float* obase = out + ((size_t)bh * SEQ + (size_t)mt * BM) * SEQ
                           + (size_t)nt * BN;
#pragma unroll
        for (int t = 0; t < 16; t++) {
            int idx = tid + t * 256;         // 0..4095
            int row = idx >> 5;              // 0..127
            int f4  = idx & 31;              // 0..31 float4 chunks
            const float4 v = *(const float4*)(ep + (size_t)row * EPI_STRIDE + f4 * 4);
            STG_CS_V4(obase + (size_t)row * SEQ + f4 * 4, v.x, v.y, v.z, v.w);
        }
    }
}

// ============================================================================
// launch
// ============================================================================
extern "C" void kernel_launch(void* const* d_in, const int* in_sizes, int n_in,
                              void* d_out, int out_size)
{
    const float* q = (const float*)d_in[0];
    const float* k = (const float*)d_in[1];
    float* out = (float*)d_out;

    cudaFuncSetAttribute(phase_gemm_kernel,
                         cudaFuncAttributeMaxDynamicSharedMemorySize, SMEM_TOTAL);

    const int NT = NBH * SEQ * (NH / 4);
    int threads = 256;
    int blocks = (2 * NT + threads - 1) / threads;
    phase_prep_kernel<<<blocks, threads>>>(q, k);

    dim3 grid(SEQ / BN, SEQ / BM, NBH);   // (16,16,16)
    phase_gemm_kernel<<<grid, 256, SMEM_TOTAL>>>(out);
}